// round 10
// baseline (speedup 1.0000x reference)
#include <cuda_runtime.h>

// OSTL one-step forward — SINGLE kernel, no partials, no second launch.
//   I      = x @ W;  u_new = sig_tau*u + I;  s = (u_new-1 > 0)
//   u_out  = u_new - s;  J_new = sig_tau*J + x[:,None]
// Outputs in d_out: [u_out (8192) | J_new (8192*8192) | s (8192)]
//
// Decomposition: each block owns a 2-float4-wide column stripe (8 floats)
// over ALL 8192 rows. Thread t handles col4 (t&1), rows (t>>1)+128*i.
// Column sums are combined with a fixed-order two-stage smem reduction
// -> deterministic, graph-safe, zero global scratch.

static constexpr int   IN_SZ  = 8192;
static constexpr int   OUT_SZ = 8192;
static constexpr int   W4PR   = OUT_SZ / 4;            // float4 per row = 2048
static constexpr float SIG_TAU = 0.8807970779778823f;  // sigmoid(2.0)

static constexpr int ITERS = IN_SZ / 128;              // 64 rows per thread

__global__ void __launch_bounds__(256, 4)
ostl_onekernel(const float* __restrict__ x,
               const float* __restrict__ u,
               const float* __restrict__ J,
               const float* __restrict__ W,
               float*       __restrict__ Jout,
               float*       __restrict__ u_out,
               float*       __restrict__ s_out)
{
    __shared__ float  xs[IN_SZ];       // 32 KiB: full x vector
    __shared__ float4 red[256];        // 4 KiB: stage-1 accs
    __shared__ float4 red2[16];        // stage-2 partials

    const int t = threadIdx.x;

    // Stage x into smem (coalesced float4).
    {
        const float4* x4 = (const float4*)x;
        float4* xs4 = (float4*)xs;
        #pragma unroll
        for (int i = 0; i < (IN_SZ / 4) / 256; ++i)
            xs4[t + 256 * i] = x4[t + 256 * i];
    }
    __syncthreads();

    const int cb4 = blockIdx.x * 2;        // block's first float4 column
    const int c4  = cb4 + (t & 1);         // this thread's float4 column
    const int r0  = t >> 1;                // starting row (0..127)

    const float4* __restrict__ J4 = (const float4*)J;
    const float4* __restrict__ W4 = (const float4*)W;
    float4*       __restrict__ O4 = (float4*)Jout;

    float a0 = 0.f, a1 = 0.f, a2 = 0.f, a3 = 0.f;

    #pragma unroll 8
    for (int i = 0; i < ITERS; ++i) {
        const int row = r0 + 128 * i;
        const float xi = xs[row];
        const size_t idx = (size_t)row * W4PR + c4;
        const float4 w = W4[idx];
        const float4 j = J4[idx];
        float4 jn;
        jn.x = fmaf(SIG_TAU, j.x, xi);
        jn.y = fmaf(SIG_TAU, j.y, xi);
        jn.z = fmaf(SIG_TAU, j.z, xi);
        jn.w = fmaf(SIG_TAU, j.w, xi);
        O4[idx] = jn;
        a0 = fmaf(xi, w.x, a0);
        a1 = fmaf(xi, w.y, a1);
        a2 = fmaf(xi, w.z, a2);
        a3 = fmaf(xi, w.w, a3);
    }

    red[t] = make_float4(a0, a1, a2, a3);
    __syncthreads();

    // Stage 1: 16 threads; thread q = (g<<1)|p sums 16 accs of parity p,
    // group g, in fixed ascending order -> deterministic.
    if (t < 16) {
        const int p = t & 1;
        const int g = t >> 1;
        float4 s4 = make_float4(0.f, 0.f, 0.f, 0.f);
        #pragma unroll
        for (int j = 0; j < 16; ++j) {
            const float4 v = red[p + 2 * (16 * g + j)];
            s4.x += v.x; s4.y += v.y; s4.z += v.z; s4.w += v.w;
        }
        red2[t] = s4;
    }
    __syncthreads();

    // Stage 2: threads 0,1 fold the 8 group partials (ascending g), then
    // apply the cell update for their float4 column.
    if (t < 2) {
        float4 tot = make_float4(0.f, 0.f, 0.f, 0.f);
        #pragma unroll
        for (int g = 0; g < 8; ++g) {
            const float4 v = red2[t + 2 * g];
            tot.x += v.x; tot.y += v.y; tot.z += v.z; tot.w += v.w;
        }
        const int oc = cb4 + t;
        const float4 uv = ((const float4*)u)[oc];
        tot.x = fmaf(SIG_TAU, uv.x, tot.x);
        tot.y = fmaf(SIG_TAU, uv.y, tot.y);
        tot.z = fmaf(SIG_TAU, uv.z, tot.z);
        tot.w = fmaf(SIG_TAU, uv.w, tot.w);

        float4 sp;
        sp.x = (tot.x - 1.0f) > 0.0f ? 1.0f : 0.0f;
        sp.y = (tot.y - 1.0f) > 0.0f ? 1.0f : 0.0f;
        sp.z = (tot.z - 1.0f) > 0.0f ? 1.0f : 0.0f;
        sp.w = (tot.w - 1.0f) > 0.0f ? 1.0f : 0.0f;

        float4 uo;
        uo.x = tot.x - sp.x;   // (V_TH - V_RESET) = 1.0
        uo.y = tot.y - sp.y;
        uo.z = tot.z - sp.z;
        uo.w = tot.w - sp.w;

        ((float4*)s_out)[oc] = sp;
        ((float4*)u_out)[oc] = uo;
    }
}

extern "C" void kernel_launch(void* const* d_in, const int* in_sizes, int n_in,
                              void* d_out, int out_size)
{
    const float* x = (const float*)d_in[0];
    const float* u = (const float*)d_in[1];
    const float* J = (const float*)d_in[2];
    const float* W = (const float*)d_in[3];

    float* out   = (float*)d_out;
    float* u_out = out;
    float* Jout  = out + OUT_SZ;
    float* s_out = out + OUT_SZ + (size_t)IN_SZ * OUT_SZ;

    ostl_onekernel<<<W4PR / 2, 256>>>(x, u, J, W, Jout, u_out, s_out);
}